// round 5
// baseline (speedup 1.0000x reference)
#include <cuda_runtime.h>
#include <math.h>

#define BATCH   16
#define NLOC    7581
#define NLOCP   7584            // padded per-anchor stride (mult of 4)
#define NANCH   22743
#define TOPK    4096
#define CAP2    131072
#define CAPS    8192
#define MAXDET  100
#define NBINS   8192
#define VECTOT  1896            // 91 + 361 + 1444 float4-chunks per (b,a)

#define NEG_INF __int_as_float(0xff800000)

__device__ float              g_objs[BATCH * 3 * NLOCP];
__device__ float              g_thr [BATCH * 3 * NLOCP];
__device__ unsigned int       g_hist[BATCH * NBINS];
__device__ unsigned int       g_lbkey[BATCH];
__device__ int                g_cnt[BATCH];
__device__ unsigned long long g_cand[(size_t)BATCH * CAP2];

__constant__ int   c_lb[3]  = {0, 361, 1805};     // unpadded loc base (for original locg)
__constant__ int   c_lbp[3] = {0, 364, 1808};     // padded loc base
__constant__ int   c_HW[3]  = {361, 1444, 5776};
__constant__ int   c_W[3]   = {19, 38, 76};
__constant__ int   c_nb[3]  = {0, 1083, 5415};
__constant__ float c_str[3] = {32.f, 16.f, 8.f};
__constant__ float c_bw2[9] = {58.f, 78.f, 186.5f,  15.f, 31.f, 29.5f,  5.f, 8.f, 16.5f};
__constant__ float c_bh2[9] = {45.f, 99.f, 163.f,   30.5f, 22.5f, 59.5f, 6.5f, 15.f, 11.5f};

__device__ __forceinline__ float sigm(float x) { return 1.f / (1.f + expf(-x)); }

__device__ __forceinline__ void vecmap(int vec, int& m, int& vbase, int& HW) {
    if (vec < 91)       { m = 0; vbase = 0;   HW = 361;  }
    else if (vec < 452) { m = 1; vbase = 91;  HW = 1444; }
    else                { m = 2; vbase = 452; HW = 5776; }
}

// ---------------- zero scratch ----------------
__global__ void zero_kernel() {
    int t = blockIdx.x * blockDim.x + threadIdx.x;
    if (t < BATCH * NBINS) g_hist[t] = 0u;
    if (t < BATCH)         g_cnt[t] = 0;
    if (t < BATCH * 3 * NLOCP) g_objs[t] = 0.f;
}

// ---------------- fused objectness + per-anchor max-class histogram ----------------
__global__ __launch_bounds__(256) void amax_kernel(const float* __restrict__ m0,
                                                   const float* __restrict__ m1,
                                                   const float* __restrict__ m2) {
    __shared__ unsigned int sh[NBINS];
    int tid = threadIdx.x;
    for (int i = tid; i < NBINS; i += 256) sh[i] = 0u;
    __syncthreads();
    int b = blockIdx.z, a = blockIdx.y;
    int vec = blockIdx.x * 256 + tid;
    if (vec < VECTOT) {
        int m, vbase, HW; vecmap(vec, m, vbase, HW);
        int locm = (vec - vbase) * 4;
        int nv = HW - locm; if (nv > 4) nv = 4;
        const float* mp = (m == 0) ? m0 : ((m == 1) ? m1 : m2);
        const float* ch0 = mp + ((size_t)(b * 255 + a * 85)) * (size_t)HW;
        float cm0 = -1e30f, cm1 = -1e30f, cm2 = -1e30f, cm3 = -1e30f;
        float o0 = 0.f, o1 = 0.f, o2 = 0.f, o3 = 0.f;
        if (m > 0) {
            const float* cls = ch0 + (size_t)5 * HW + locm;
#pragma unroll 10
            for (int ch = 0; ch < 80; ++ch) {
                float4 v = __ldg((const float4*)(cls + (size_t)ch * HW));
                cm0 = fmaxf(cm0, v.x); cm1 = fmaxf(cm1, v.y);
                cm2 = fmaxf(cm2, v.z); cm3 = fmaxf(cm3, v.w);
            }
            float4 ov = __ldg((const float4*)(ch0 + (size_t)4 * HW + locm));
            o0 = ov.x; o1 = ov.y; o2 = ov.z; o3 = ov.w;
        } else {
            const float* cls = ch0 + (size_t)5 * HW + locm;
            for (int ch = 0; ch < 80; ++ch) {
                const float* r = cls + (size_t)ch * HW;
                cm0 = fmaxf(cm0, r[0]);
                if (nv > 1) cm1 = fmaxf(cm1, r[1]);
                if (nv > 2) cm2 = fmaxf(cm2, r[2]);
                if (nv > 3) cm3 = fmaxf(cm3, r[3]);
            }
            const float* orow = ch0 + (size_t)4 * HW + locm;
            o0 = orow[0];
            if (nv > 1) o1 = orow[1];
            if (nv > 2) o2 = orow[2];
            if (nv > 3) o3 = orow[3];
        }
        float cmv[4] = {cm0, cm1, cm2, cm3};
        float tov[4] = {o0, o1, o2, o3};
        int obase = (b * 3 + a) * NLOCP + c_lbp[m] + locm;
#pragma unroll
        for (int e = 0; e < 4; e++) {
            if (e < nv) {
                float obj = sigm(tov[e]);
                g_objs[obase + e] = obj;
                float cs = sigm(cmv[e]);
                unsigned int key = (obj >= 0.005f && cs > 0.05f)
                                       ? (__float_as_uint(cs * obj) | 0x80000000u) : 0u;
                atomicAdd(&sh[key >> 19], 1u);
            }
        }
    }
    __syncthreads();
    for (int i = tid; i < NBINS; i += 256) {
        unsigned int v = sh[i];
        if (v) atomicAdd(&g_hist[b * NBINS + i], v);
    }
}

// ---- parallel top-down bin finder over an 8192-bin smem histogram (1024 thr) ----
__device__ __forceinline__ void find_bin_top(const unsigned int* hist, int K,
                                             int* part, int* wsum,
                                             int* out_bin, int* out_above) {
    int tid = threadIdx.x;
    int s = 0;
#pragma unroll
    for (int k = 0; k < 8; k++) s += (int)hist[tid * 8 + k];
    part[tid] = s;
    int v = s;
    for (int o = 16; o; o >>= 1) v += __shfl_xor_sync(0xffffffffu, v, o);
    if ((tid & 31) == 0) wsum[tid >> 5] = v;
    __syncthreads();
    if (tid == 0) {
        int cum = 0, bin = 0, wi;
        for (wi = 31; wi >= 0; --wi) {
            if (cum + wsum[wi] >= K) break;
            cum += wsum[wi];
        }
        if (wi >= 0) {
            int p;
            for (p = wi * 32 + 31; p > wi * 32; --p) {
                if (cum + part[p] >= K) break;
                cum += part[p];
            }
            int bb;
            for (bb = p * 8 + 7; bb > p * 8; --bb) {
                if (cum + (int)hist[bb] >= K) break;
                cum += (int)hist[bb];
            }
            bin = bb;
        }
        *out_bin = bin; *out_above = cum;
    }
    __syncthreads();
}

// ---------------- LB + per-anchor raw-logit thresholds ----------------
__global__ __launch_bounds__(1024) void thr_kernel() {
    __shared__ unsigned int h[NBINS];
    __shared__ int part[1024];
    __shared__ int wsum[32];
    __shared__ int sbin, sabove;
    int b = blockIdx.x, tid = threadIdx.x;
    for (int i = tid; i < NBINS; i += 1024) h[i] = g_hist[b * NBINS + i];
    __syncthreads();
    find_bin_top(h, TOPK, part, wsum, &sbin, &sabove);
    unsigned int lbkey = ((unsigned int)sbin) << 19;
    if (tid == 0) g_lbkey[b] = lbkey;
    float LB = __uint_as_float(lbkey & 0x7FFFFFFFu);
    for (int r = tid; r < 3 * NLOCP; r += 1024) {
        float obj = g_objs[b * 3 * NLOCP + r];
        float thr;
        if (obj < 0.005f) thr = 3.0e38f;
        else if (LB <= 0.f) thr = -2.9446f;
        else {
            float ratio = LB / obj;
            if (ratio >= 1.0f) thr = 3.0e38f;
            else thr = fmaxf(logf(ratio / (1.0f - ratio)) - 1e-2f, -2.9446f);
        }
        g_thr[b * 3 * NLOCP + r] = thr;
    }
}

// ---------------- candidate generation (vectorized: 4 locations/thread) ----------------
__global__ __launch_bounds__(256) void cand_kernel(const float* __restrict__ m0,
                                                   const float* __restrict__ m1,
                                                   const float* __restrict__ m2) {
    int b = blockIdx.z;
    int ac = blockIdx.y;
    int a = ac / 80, cl = ac - a * 80;
    int vec = blockIdx.x * 256 + threadIdx.x;
    unsigned int lbk = g_lbkey[b];

    float cv0 = -1e30f, cv1 = -1e30f, cv2 = -1e30f, cv3 = -1e30f;
    float tv0 = 3e38f, tv1 = 3e38f, tv2 = 3e38f, tv3 = 3e38f;
    int m = 0, locm = 0, nv = 0, pbase = 0;
    if (vec < VECTOT) {
        int vbase, HW; vecmap(vec, m, vbase, HW);
        locm = (vec - vbase) * 4;
        nv = HW - locm; if (nv > 4) nv = 4;
        const float* mp = (m == 0) ? m0 : ((m == 1) ? m1 : m2);
        const float* cr = mp + ((size_t)(b * 255 + a * 85 + 5 + cl)) * (size_t)HW + locm;
        pbase = (b * 3 + a) * NLOCP + c_lbp[m] + locm;
        float4 tv = *(const float4*)(g_thr + pbase);
        tv0 = tv.x; tv1 = tv.y; tv2 = tv.z; tv3 = tv.w;
        if (m > 0) {
            float4 c4 = __ldg((const float4*)cr);
            cv0 = c4.x; cv1 = c4.y; cv2 = c4.z; cv3 = c4.w;
        } else {
            cv0 = cr[0];
            if (nv > 1) cv1 = cr[1];
            if (nv > 2) cv2 = cr[2];
            if (nv > 3) cv3 = cr[3];
        }
    }
    float cva[4] = {cv0, cv1, cv2, cv3};
    float tva[4] = {tv0, tv1, tv2, tv3};
    int lane = threadIdx.x & 31;
#pragma unroll
    for (int e = 0; e < 4; e++) {
        bool emit = false;
        unsigned long long pk = 0ull;
        if (e < nv && cva[e] >= tva[e]) {
            float obj = g_objs[pbase + e];
            float cs = sigm(cva[e]);
            if (cs > 0.05f && obj >= 0.005f) {
                unsigned int key = __float_as_uint(cs * obj) | 0x80000000u;
                if (key >= lbk) {
                    int nI = c_nb[m] + (locm + e) * 3 + a;
                    unsigned int idx = (unsigned int)nI * 80u + (unsigned int)cl;
                    pk = (((unsigned long long)(~key)) << 32) | (unsigned long long)idx;
                    emit = true;
                }
            }
        }
        unsigned int mask = __ballot_sync(0xffffffffu, emit);
        if (mask) {
            int leader = __ffs(mask) - 1;
            int basep = 0;
            if (lane == leader) basep = atomicAdd(&g_cnt[b], __popc(mask));
            basep = __shfl_sync(0xffffffffu, basep, leader);
            if (emit) {
                int pos = basep + __popc(mask & ((1u << lane) - 1u));
                if (pos < CAP2) g_cand[(size_t)b * CAP2 + pos] = pk;
            }
        }
    }
}

// ---------------- select + sort + decode + NMS (one block per image) ----------------
__global__ __launch_bounds__(1024) void finish_kernel(const float* __restrict__ m0,
                                                      const float* __restrict__ m1,
                                                      const float* __restrict__ m2,
                                                      float* __restrict__ out, int out_size) {
    extern __shared__ char smraw[];
    unsigned long long* scand = (unsigned long long*)smraw;          // 64 KB
    char* nb = smraw + 65536;
    float4* sbox = (float4*)nb;                                      // 64 KB
    float*  ss   = (float*)(nb + 65536);                             // 16 KB
    float*  soff = (float*)(nb + 81920);                             // 16 KB
    int*    slbl = (int*)(nb + 98304);                               // 16 KB
    unsigned int* hist = (unsigned int*)nb;                          // pre-sort only
    __shared__ int part[1024];
    __shared__ int wsum[32];
    __shared__ unsigned int salive[128];
    __shared__ float wred[32];
    __shared__ int st2, sgt, st3, sdum, scc;
    __shared__ int sj, skeep, sfrontw;
    __shared__ float smaxc;

    int b = blockIdx.x, tid = threadIdx.x;
    int n = g_cnt[b]; if (n > CAP2) n = CAP2;
    const unsigned long long* cand = g_cand + (size_t)b * CAP2;

    for (int i = tid; i < NBINS; i += 1024) hist[i] = 0u;
    __syncthreads();
    for (int i = tid; i < n; i += 1024) {
        unsigned int key = ~(unsigned int)(cand[i] >> 32);
        atomicAdd(&hist[key >> 19], 1u);
    }
    __syncthreads();
    find_bin_top(hist, TOPK, part, wsum, &st2, &sgt);
    int t2 = st2, gt = sgt;
    __syncthreads();
    for (int i = tid; i < NBINS; i += 1024) hist[i] = 0u;
    __syncthreads();
    for (int i = tid; i < n; i += 1024) {
        unsigned int key = ~(unsigned int)(cand[i] >> 32);
        if ((int)(key >> 19) == t2) atomicAdd(&hist[(key >> 6) & 0x1FFFu], 1u);
    }
    __syncthreads();
    find_bin_top(hist, TOPK - gt, part, wsum, &st3, &sdum);
    int t3 = st3;
    if (tid == 0) scc = 0;
    __syncthreads();
    for (int i = tid; i < n; i += 1024) {
        unsigned long long e = cand[i];
        unsigned int key = ~(unsigned int)(e >> 32);
        int hb = (int)(key >> 19);
        bool keep = (hb > t2) || (hb == t2 && (int)((key >> 6) & 0x1FFFu) >= t3);
        if (keep) {
            int p = atomicAdd(&scc, 1);
            if (p < CAPS) scand[p] = e;
        }
    }
    __syncthreads();
    int c2 = scc; if (c2 > CAPS) c2 = CAPS;
    for (int i = tid; i < CAPS; i += 1024)
        if (i >= c2) scand[i] = 0xFFFFFFFFFFFFFFFFull;
    __syncthreads();
    for (int k = 2; k <= CAPS; k <<= 1) {
        for (int j = k >> 1; j > 0; j >>= 1) {
            for (int i = tid; i < CAPS; i += 1024) {
                int ix = i ^ j;
                if (ix > i) {
                    unsigned long long A = scand[i], B = scand[ix];
                    bool up = ((i & k) == 0);
                    if ((A > B) == up) { scand[i] = B; scand[ix] = A; }
                }
            }
            __syncthreads();
        }
    }
    float lmax = NEG_INF;
#pragma unroll
    for (int k2 = 0; k2 < 4; k2++) {
        int i = k2 * 1024 + tid;
        unsigned long long e = scand[i];
        unsigned int key = ~(unsigned int)(e >> 32);
        unsigned int idx = (unsigned int)e;
        float sc; float4 bx = make_float4(0.f, 0.f, 0.f, 0.f); int lbl = 0;
        bool alive = (key != 0u);
        if (alive) {
            sc = __uint_as_float(key & 0x7FFFFFFFu);
            int nI = (int)(idx / 80u); lbl = (int)idx - nI * 80;
            int m = (nI < 1083) ? 0 : ((nI < 5415) ? 1 : 2);
            int rem = nI - c_nb[m];
            int locm = rem / 3, a = rem - locm * 3;
            const float* mp = (m == 0) ? m0 : ((m == 1) ? m1 : m2);
            size_t HW = (size_t)c_HW[m];
            const float* bp = mp + ((size_t)b * 255 + a * 85) * HW + locm;
            float tx = bp[0], ty = bp[HW], tw = bp[2 * HW], th = bp[3 * HW];
            float s = c_str[m]; int W = c_W[m];
            int hh = locm / W, ww = locm - hh * W;
            float sx = sigm(tx), sy = sigm(ty);
            float cx = (float)ww * s + 0.5f * s + (sx - 0.5f) * s;
            float cy = (float)hh * s + 0.5f * s + (sy - 0.5f) * s;
            float wx = c_bw2[m * 3 + a] * expf(tw);
            float wy = c_bh2[m * 3 + a] * expf(th);
            bx = make_float4(cx - wx, cy - wy, cx + wx, cy + wy);
        } else sc = NEG_INF;
        sbox[i] = bx; ss[i] = sc; slbl[i] = lbl;
        unsigned int bal = __ballot_sync(0xffffffffu, alive);
        if ((tid & 31) == 0) salive[k2 * 32 + (tid >> 5)] = bal;
        float rm = alive ? fmaxf(fmaxf(bx.x, bx.y), fmaxf(bx.z, bx.w)) : 0.f;
        lmax = fmaxf(lmax, rm);
    }
    for (int o = 16; o; o >>= 1) lmax = fmaxf(lmax, __shfl_xor_sync(0xffffffffu, lmax, o));
    if ((tid & 31) == 0) wred[tid >> 5] = lmax;
    __syncthreads();
    if (tid < 32) {
        float v = wred[tid];
        for (int o = 16; o; o >>= 1) v = fmaxf(v, __shfl_xor_sync(0xffffffffu, v, o));
        if (tid == 0) { smaxc = v; sfrontw = 0; }
    }
    __syncthreads();
    float ob = smaxc + 1.0f;
    for (int i = tid; i < TOPK; i += 1024) soff[i] = (float)slbl[i] * ob;
    __syncthreads();

    for (int it = 0; it < MAXDET; ++it) {
        if (tid < 32) {
            int fw = sfrontw;
            int j = -1;
            while (fw < 128) {
                unsigned int wv = (fw + tid < 128) ? salive[fw + tid] : 0u;
                unsigned int bal = __ballot_sync(0xffffffffu, wv != 0u);
                if (bal) {
                    int wl = __ffs(bal) - 1;
                    unsigned int w2 = __shfl_sync(0xffffffffu, wv, wl);
                    j = (fw + wl) * 32 + (__ffs(w2) - 1);
                    if (tid == 0) sfrontw = fw + wl;
                    break;
                }
                fw += 32;
            }
            if (tid == 0) {
                skeep = (j >= 0) ? 1 : 0;
                sj = (j >= 0) ? j : 0;
                if (j >= 0) {
                    float* o = out + (size_t)(b * MAXDET + it) * 5;
                    float4 bxj = sbox[j];
                    o[0] = bxj.x; o[1] = bxj.y; o[2] = bxj.z; o[3] = bxj.w; o[4] = ss[j];
                    if (out_size > BATCH * MAXDET * 5)
                        out[BATCH * MAXDET * 5 + b * MAXDET + it] = (float)slbl[j];
                }
            }
        }
        __syncthreads();
        if (!skeep) {
            for (int r = it + tid; r < MAXDET; r += 1024) {
                float* o = out + (size_t)(b * MAXDET + r) * 5;
                o[0] = 0.f; o[1] = 0.f; o[2] = 0.f; o[3] = 0.f; o[4] = 0.f;
                if (out_size > BATCH * MAXDET * 5)
                    out[BATCH * MAXDET * 5 + b * MAXDET + r] = -1.0f;
            }
            break;
        }
        int j = sj;
        float oj = soff[j];
        float4 bj = sbox[j];
        float jx0 = bj.x + oj, jy0 = bj.y + oj, jx1 = bj.z + oj, jy1 = bj.w + oj;
        float a1 = (jx1 - jx0) * (jy1 - jy0);
#pragma unroll
        for (int k2 = 0; k2 < 4; k2++) {
            int i = k2 * 1024 + tid;
            float sct = ss[i];
            bool aliveN = (sct != NEG_INF);
            if (aliveN) {
                float ot = soff[i]; float4 bt = sbox[i];
                float tx0 = bt.x + ot, ty0 = bt.y + ot, tx1 = bt.z + ot, ty1 = bt.w + ot;
                float tlx = fmaxf(jx0, tx0), tly = fmaxf(jy0, ty0);
                float brx = fminf(jx1, tx1), bry = fminf(jy1, ty1);
                float iw = fmaxf(brx - tlx, 0.f), ih = fmaxf(bry - tly, 0.f);
                float inter = iw * ih;
                float a2 = (tx1 - tx0) * (ty1 - ty0);
                float iou = inter / (a1 + a2 - inter + 1e-12f);
                if (iou > 0.45f) { ss[i] = NEG_INF; aliveN = false; }
            }
            unsigned int bal = __ballot_sync(0xffffffffu, aliveN);
            if ((tid & 31) == 0) salive[k2 * 32 + (tid >> 5)] = bal;
        }
        __syncthreads();
    }
}

// ---------------- launcher ----------------
extern "C" void kernel_launch(void* const* d_in, const int* in_sizes, int n_in,
                              void* d_out, int out_size) {
    const float* m0 = (const float*)d_in[0];
    const float* m1 = (const float*)d_in[1];
    const float* m2 = (const float*)d_in[2];
    float* out = (float*)d_out;

    cudaFuncSetAttribute(finish_kernel, cudaFuncAttributeMaxDynamicSharedMemorySize, 180224);

    zero_kernel<<<(BATCH * 3 * NLOCP + 255) / 256, 256>>>();
    amax_kernel<<<dim3((VECTOT + 255) / 256, 3, BATCH), 256>>>(m0, m1, m2);
    thr_kernel<<<BATCH, 1024>>>();
    cand_kernel<<<dim3((VECTOT + 255) / 256, 240, BATCH), 256>>>(m0, m1, m2);
    finish_kernel<<<BATCH, 1024, 180224>>>(m0, m1, m2, out, out_size);
}

// round 6
// speedup vs baseline: 1.5761x; 1.5761x over previous
#include <cuda_runtime.h>
#include <math.h>

#define BATCH   16
#define NLOC    7581
#define NLOCP   7584
#define NANCH   22743
#define TOPK    4096
#define CAP2    131072
#define CAPS    8192
#define MAXDET  100
#define NBINS   8192
#define VECTOT  1896            // 91 + 361 + 1444 float4-chunks per (b,a)

#define NEG_INF __int_as_float(0xff800000)

__device__ float              g_objs[BATCH * 3 * NLOCP];
__device__ float              g_thr [BATCH * 3 * NLOCP];
__device__ unsigned int       g_hist[BATCH * NBINS];
__device__ unsigned int       g_lbkey[BATCH];
__device__ int                g_cnt[BATCH];
__device__ unsigned long long g_cand[(size_t)BATCH * CAP2];

__constant__ int   c_lb[3]  = {0, 361, 1805};
__constant__ int   c_lbp[3] = {0, 364, 1808};
__constant__ int   c_HW[3]  = {361, 1444, 5776};
__constant__ int   c_W[3]   = {19, 38, 76};
__constant__ int   c_nb[3]  = {0, 1083, 5415};
__constant__ float c_str[3] = {32.f, 16.f, 8.f};
__constant__ float c_bw2[9] = {58.f, 78.f, 186.5f,  15.f, 31.f, 29.5f,  5.f, 8.f, 16.5f};
__constant__ float c_bh2[9] = {45.f, 99.f, 163.f,   30.5f, 22.5f, 59.5f, 6.5f, 15.f, 11.5f};

__device__ __forceinline__ float sigm(float x) { return 1.f / (1.f + expf(-x)); }

__device__ __forceinline__ void vecmap(int vec, int& m, int& vbase, int& HW) {
    if (vec < 91)       { m = 0; vbase = 0;   HW = 361;  }
    else if (vec < 452) { m = 1; vbase = 91;  HW = 1444; }
    else                { m = 2; vbase = 452; HW = 5776; }
}

// ---------------- zero scratch ----------------
__global__ void zero_kernel() {
    int t = blockIdx.x * blockDim.x + threadIdx.x;
    if (t < BATCH * NBINS) g_hist[t] = 0u;
    if (t < BATCH)         g_cnt[t] = 0;
    if (t < BATCH * 3 * NLOCP) g_objs[t] = 0.f;
}

// ---------------- fused objectness + per-anchor max-class histogram ----------------
__global__ __launch_bounds__(256) void amax_kernel(const float* __restrict__ m0,
                                                   const float* __restrict__ m1,
                                                   const float* __restrict__ m2) {
    __shared__ unsigned int sh[NBINS];
    int tid = threadIdx.x;
    for (int i = tid; i < NBINS; i += 256) sh[i] = 0u;
    __syncthreads();
    int b = blockIdx.z, a = blockIdx.y;
    int vec = blockIdx.x * 256 + tid;
    if (vec < VECTOT) {
        int m, vbase, HW; vecmap(vec, m, vbase, HW);
        int locm = (vec - vbase) * 4;
        int nv = HW - locm; if (nv > 4) nv = 4;
        const float* mp = (m == 0) ? m0 : ((m == 1) ? m1 : m2);
        const float* ch0 = mp + ((size_t)(b * 255 + a * 85)) * (size_t)HW;
        float cm0 = -1e30f, cm1 = -1e30f, cm2 = -1e30f, cm3 = -1e30f;
        float o0 = 0.f, o1 = 0.f, o2 = 0.f, o3 = 0.f;
        if (m > 0) {
            const float* cls = ch0 + (size_t)5 * HW + locm;
#pragma unroll 10
            for (int ch = 0; ch < 80; ++ch) {
                float4 v = __ldg((const float4*)(cls + (size_t)ch * HW));
                cm0 = fmaxf(cm0, v.x); cm1 = fmaxf(cm1, v.y);
                cm2 = fmaxf(cm2, v.z); cm3 = fmaxf(cm3, v.w);
            }
            float4 ov = __ldg((const float4*)(ch0 + (size_t)4 * HW + locm));
            o0 = ov.x; o1 = ov.y; o2 = ov.z; o3 = ov.w;
        } else {
            const float* cls = ch0 + (size_t)5 * HW + locm;
            for (int ch = 0; ch < 80; ++ch) {
                const float* r = cls + (size_t)ch * HW;
                cm0 = fmaxf(cm0, r[0]);
                if (nv > 1) cm1 = fmaxf(cm1, r[1]);
                if (nv > 2) cm2 = fmaxf(cm2, r[2]);
                if (nv > 3) cm3 = fmaxf(cm3, r[3]);
            }
            const float* orow = ch0 + (size_t)4 * HW + locm;
            o0 = orow[0];
            if (nv > 1) o1 = orow[1];
            if (nv > 2) o2 = orow[2];
            if (nv > 3) o3 = orow[3];
        }
        float cmv[4] = {cm0, cm1, cm2, cm3};
        float tov[4] = {o0, o1, o2, o3};
        int obase = (b * 3 + a) * NLOCP + c_lbp[m] + locm;
#pragma unroll
        for (int e = 0; e < 4; e++) {
            if (e < nv) {
                float obj = sigm(tov[e]);
                g_objs[obase + e] = obj;
                float cs = sigm(cmv[e]);
                unsigned int key = (obj >= 0.005f && cs > 0.05f)
                                       ? (__float_as_uint(cs * obj) | 0x80000000u) : 0u;
                atomicAdd(&sh[key >> 19], 1u);
            }
        }
    }
    __syncthreads();
    for (int i = tid; i < NBINS; i += 256) {
        unsigned int v = sh[i];
        if (v) atomicAdd(&g_hist[b * NBINS + i], v);
    }
}

// ---- parallel top-down bin finder over an 8192-bin smem histogram (1024 thr) ----
__device__ __forceinline__ void find_bin_top(const unsigned int* hist, int K,
                                             int* part, int* wsum,
                                             int* out_bin, int* out_above) {
    int tid = threadIdx.x;
    int s = 0;
#pragma unroll
    for (int k = 0; k < 8; k++) s += (int)hist[tid * 8 + k];
    part[tid] = s;
    int v = s;
    for (int o = 16; o; o >>= 1) v += __shfl_xor_sync(0xffffffffu, v, o);
    if ((tid & 31) == 0) wsum[tid >> 5] = v;
    __syncthreads();
    if (tid == 0) {
        int cum = 0, bin = 0, wi;
        for (wi = 31; wi >= 0; --wi) {
            if (cum + wsum[wi] >= K) break;
            cum += wsum[wi];
        }
        if (wi >= 0) {
            int p;
            for (p = wi * 32 + 31; p > wi * 32; --p) {
                if (cum + part[p] >= K) break;
                cum += part[p];
            }
            int bb;
            for (bb = p * 8 + 7; bb > p * 8; --bb) {
                if (cum + (int)hist[bb] >= K) break;
                cum += (int)hist[bb];
            }
            bin = bb;
        }
        *out_bin = bin; *out_above = cum;
    }
    __syncthreads();
}

// ---------------- LB + per-anchor raw-logit thresholds ----------------
__global__ __launch_bounds__(1024) void thr_kernel() {
    __shared__ unsigned int h[NBINS];
    __shared__ int part[1024];
    __shared__ int wsum[32];
    __shared__ int sbin, sabove;
    int b = blockIdx.x, tid = threadIdx.x;
    for (int i = tid; i < NBINS; i += 1024) h[i] = g_hist[b * NBINS + i];
    __syncthreads();
    find_bin_top(h, TOPK, part, wsum, &sbin, &sabove);
    unsigned int lbkey = ((unsigned int)sbin) << 19;
    if (tid == 0) g_lbkey[b] = lbkey;
    float LB = __uint_as_float(lbkey & 0x7FFFFFFFu);
    for (int r = tid; r < 3 * NLOCP; r += 1024) {
        float obj = g_objs[b * 3 * NLOCP + r];
        float thr;
        if (obj < 0.005f) thr = 3.0e38f;
        else if (LB <= 0.f) thr = -2.9446f;
        else {
            float ratio = LB / obj;
            if (ratio >= 1.0f) thr = 3.0e38f;
            else thr = fmaxf(logf(ratio / (1.0f - ratio)) - 1e-2f, -2.9446f);
        }
        g_thr[b * 3 * NLOCP + r] = thr;
    }
}

// ---------------- candidate generation (block-aggregated compaction) ----------------
// 512 threads, each handles 2 float4 chunks (8 locations). grid (2, 240, 16).
__global__ __launch_bounds__(512) void cand_kernel(const float* __restrict__ m0,
                                                   const float* __restrict__ m1,
                                                   const float* __restrict__ m2) {
    __shared__ unsigned long long sbuf[4096];
    __shared__ int scnt;
    __shared__ int sbase;
    int b = blockIdx.z;
    int ac = blockIdx.y;
    int a = ac / 80, cl = ac - a * 80;
    int tid = threadIdx.x;
    if (tid == 0) scnt = 0;
    __syncthreads();
    unsigned int lbk = g_lbkey[b];

#pragma unroll
    for (int half = 0; half < 2; half++) {
        int vec = blockIdx.x * 1024 + half * 512 + tid;
        if (vec < VECTOT) {
            int m, vbase, HW; vecmap(vec, m, vbase, HW);
            int locm = (vec - vbase) * 4;
            int nv = HW - locm; if (nv > 4) nv = 4;
            const float* mp = (m == 0) ? m0 : ((m == 1) ? m1 : m2);
            const float* cr = mp + ((size_t)(b * 255 + a * 85 + 5 + cl)) * (size_t)HW + locm;
            int pbase = (b * 3 + a) * NLOCP + c_lbp[m] + locm;
            float4 tv = *(const float4*)(g_thr + pbase);
            float cva[4], tva[4] = {tv.x, tv.y, tv.z, tv.w};
            if (m > 0) {
                float4 c4 = __ldg((const float4*)cr);
                cva[0] = c4.x; cva[1] = c4.y; cva[2] = c4.z; cva[3] = c4.w;
            } else {
                cva[0] = cr[0];
                cva[1] = (nv > 1) ? cr[1] : -1e30f;
                cva[2] = (nv > 2) ? cr[2] : -1e30f;
                cva[3] = (nv > 3) ? cr[3] : -1e30f;
            }
#pragma unroll
            for (int e = 0; e < 4; e++) {
                if (e < nv && cva[e] >= tva[e]) {
                    float obj = g_objs[pbase + e];
                    float cs = sigm(cva[e]);
                    if (cs > 0.05f && obj >= 0.005f) {
                        unsigned int key = __float_as_uint(cs * obj) | 0x80000000u;
                        if (key >= lbk) {
                            int nI = c_nb[m] + (locm + e) * 3 + a;
                            unsigned int idx = (unsigned int)nI * 80u + (unsigned int)cl;
                            int p = atomicAdd(&scnt, 1);
                            sbuf[p] = (((unsigned long long)(~key)) << 32)
                                      | (unsigned long long)idx;
                        }
                    }
                }
            }
        }
    }
    __syncthreads();
    int c = scnt;
    if (c > 0) {
        if (tid == 0) sbase = atomicAdd(&g_cnt[b], c);
        __syncthreads();
        int gb = sbase;
        for (int i = tid; i < c; i += 512) {
            int pos = gb + i;
            if (pos < CAP2) g_cand[(size_t)b * CAP2 + pos] = sbuf[i];
        }
    }
}

// ---------------- select + sort + decode + NMS (one block per image) ----------------
__global__ __launch_bounds__(1024) void finish_kernel(const float* __restrict__ m0,
                                                      const float* __restrict__ m1,
                                                      const float* __restrict__ m2,
                                                      float* __restrict__ out, int out_size) {
    extern __shared__ char smraw[];
    unsigned long long* scand = (unsigned long long*)smraw;          // 64 KB
    char* nb = smraw + 65536;
    float4* sbox = (float4*)nb;                                      // 64 KB
    float*  ss   = (float*)(nb + 65536);                             // 16 KB
    float*  soff = (float*)(nb + 81920);                             // 16 KB
    int*    slbl = (int*)(nb + 98304);                               // 16 KB
    unsigned int* hist = (unsigned int*)nb;                          // pre-sort only
    __shared__ int part[1024];
    __shared__ int wsum[32];
    __shared__ unsigned int salive[128];
    __shared__ float wred[32];
    __shared__ int st2, sgt, st3, sdum, scc;
    __shared__ int sj, skeep, sfrontw;
    __shared__ float smaxc;

    int b = blockIdx.x, tid = threadIdx.x;
    int n = g_cnt[b]; if (n > CAP2) n = CAP2;
    const unsigned long long* cand = g_cand + (size_t)b * CAP2;

    for (int i = tid; i < NBINS; i += 1024) hist[i] = 0u;
    __syncthreads();
    for (int i = tid; i < n; i += 1024) {
        unsigned int key = ~(unsigned int)(cand[i] >> 32);
        atomicAdd(&hist[key >> 19], 1u);
    }
    __syncthreads();
    find_bin_top(hist, TOPK, part, wsum, &st2, &sgt);
    int t2 = st2, gt = sgt;
    __syncthreads();
    for (int i = tid; i < NBINS; i += 1024) hist[i] = 0u;
    __syncthreads();
    for (int i = tid; i < n; i += 1024) {
        unsigned int key = ~(unsigned int)(cand[i] >> 32);
        if ((int)(key >> 19) == t2) atomicAdd(&hist[(key >> 6) & 0x1FFFu], 1u);
    }
    __syncthreads();
    find_bin_top(hist, TOPK - gt, part, wsum, &st3, &sdum);
    int t3 = st3;
    if (tid == 0) scc = 0;
    __syncthreads();
    for (int i = tid; i < n; i += 1024) {
        unsigned long long e = cand[i];
        unsigned int key = ~(unsigned int)(e >> 32);
        int hb = (int)(key >> 19);
        bool keep = (hb > t2) || (hb == t2 && (int)((key >> 6) & 0x1FFFu) >= t3);
        if (keep) {
            int p = atomicAdd(&scc, 1);
            if (p < CAPS) scand[p] = e;
        }
    }
    __syncthreads();
    int c2 = scc; if (c2 > CAPS) c2 = CAPS;
    for (int i = tid; i < CAPS; i += 1024)
        if (i >= c2) scand[i] = 0xFFFFFFFFFFFFFFFFull;
    __syncthreads();
    for (int k = 2; k <= CAPS; k <<= 1) {
        for (int j = k >> 1; j > 0; j >>= 1) {
            for (int i = tid; i < CAPS; i += 1024) {
                int ix = i ^ j;
                if (ix > i) {
                    unsigned long long A = scand[i], B = scand[ix];
                    bool up = ((i & k) == 0);
                    if ((A > B) == up) { scand[i] = B; scand[ix] = A; }
                }
            }
            __syncthreads();
        }
    }
    float lmax = NEG_INF;
#pragma unroll
    for (int k2 = 0; k2 < 4; k2++) {
        int i = k2 * 1024 + tid;
        unsigned long long e = scand[i];
        unsigned int key = ~(unsigned int)(e >> 32);
        unsigned int idx = (unsigned int)e;
        float sc; float4 bx = make_float4(0.f, 0.f, 0.f, 0.f); int lbl = 0;
        bool alive = (key != 0u);
        if (alive) {
            sc = __uint_as_float(key & 0x7FFFFFFFu);
            int nI = (int)(idx / 80u); lbl = (int)idx - nI * 80;
            int m = (nI < 1083) ? 0 : ((nI < 5415) ? 1 : 2);
            int rem = nI - c_nb[m];
            int locm = rem / 3, a = rem - locm * 3;
            const float* mp = (m == 0) ? m0 : ((m == 1) ? m1 : m2);
            size_t HW = (size_t)c_HW[m];
            const float* bp = mp + ((size_t)b * 255 + a * 85) * HW + locm;
            float tx = bp[0], ty = bp[HW], tw = bp[2 * HW], th = bp[3 * HW];
            float s = c_str[m]; int W = c_W[m];
            int hh = locm / W, ww = locm - hh * W;
            float sx = sigm(tx), sy = sigm(ty);
            float cx = (float)ww * s + 0.5f * s + (sx - 0.5f) * s;
            float cy = (float)hh * s + 0.5f * s + (sy - 0.5f) * s;
            float wx = c_bw2[m * 3 + a] * expf(tw);
            float wy = c_bh2[m * 3 + a] * expf(th);
            bx = make_float4(cx - wx, cy - wy, cx + wx, cy + wy);
        } else sc = NEG_INF;
        sbox[i] = bx; ss[i] = sc; slbl[i] = lbl;
        unsigned int bal = __ballot_sync(0xffffffffu, alive);
        if ((tid & 31) == 0) salive[k2 * 32 + (tid >> 5)] = bal;
        float rm = alive ? fmaxf(fmaxf(bx.x, bx.y), fmaxf(bx.z, bx.w)) : 0.f;
        lmax = fmaxf(lmax, rm);
    }
    for (int o = 16; o; o >>= 1) lmax = fmaxf(lmax, __shfl_xor_sync(0xffffffffu, lmax, o));
    if ((tid & 31) == 0) wred[tid >> 5] = lmax;
    __syncthreads();
    if (tid < 32) {
        float v = wred[tid];
        for (int o = 16; o; o >>= 1) v = fmaxf(v, __shfl_xor_sync(0xffffffffu, v, o));
        if (tid == 0) { smaxc = v; sfrontw = 0; }
    }
    __syncthreads();
    float ob = smaxc + 1.0f;
    for (int i = tid; i < TOPK; i += 1024) soff[i] = (float)slbl[i] * ob;
    __syncthreads();

    for (int it = 0; it < MAXDET; ++it) {
        if (tid < 32) {
            int fw = sfrontw;
            int j = -1;
            while (fw < 128) {
                unsigned int wv = (fw + tid < 128) ? salive[fw + tid] : 0u;
                unsigned int bal = __ballot_sync(0xffffffffu, wv != 0u);
                if (bal) {
                    int wl = __ffs(bal) - 1;
                    unsigned int w2 = __shfl_sync(0xffffffffu, wv, wl);
                    j = (fw + wl) * 32 + (__ffs(w2) - 1);
                    if (tid == 0) sfrontw = fw + wl;
                    break;
                }
                fw += 32;
            }
            if (tid == 0) {
                skeep = (j >= 0) ? 1 : 0;
                sj = (j >= 0) ? j : 0;
                if (j >= 0) {
                    float* o = out + (size_t)(b * MAXDET + it) * 5;
                    float4 bxj = sbox[j];
                    o[0] = bxj.x; o[1] = bxj.y; o[2] = bxj.z; o[3] = bxj.w; o[4] = ss[j];
                    if (out_size > BATCH * MAXDET * 5)
                        out[BATCH * MAXDET * 5 + b * MAXDET + it] = (float)slbl[j];
                }
            }
        }
        __syncthreads();
        if (!skeep) {
            for (int r = it + tid; r < MAXDET; r += 1024) {
                float* o = out + (size_t)(b * MAXDET + r) * 5;
                o[0] = 0.f; o[1] = 0.f; o[2] = 0.f; o[3] = 0.f; o[4] = 0.f;
                if (out_size > BATCH * MAXDET * 5)
                    out[BATCH * MAXDET * 5 + b * MAXDET + r] = -1.0f;
            }
            break;
        }
        int j = sj;
        float oj = soff[j];
        float4 bj = sbox[j];
        float jx0 = bj.x + oj, jy0 = bj.y + oj, jx1 = bj.z + oj, jy1 = bj.w + oj;
        float a1 = (jx1 - jx0) * (jy1 - jy0);
#pragma unroll
        for (int k2 = 0; k2 < 4; k2++) {
            int i = k2 * 1024 + tid;
            float sct = ss[i];
            bool aliveN = (sct != NEG_INF);
            if (aliveN) {
                float ot = soff[i]; float4 bt = sbox[i];
                float tx0 = bt.x + ot, ty0 = bt.y + ot, tx1 = bt.z + ot, ty1 = bt.w + ot;
                float tlx = fmaxf(jx0, tx0), tly = fmaxf(jy0, ty0);
                float brx = fminf(jx1, tx1), bry = fminf(jy1, ty1);
                float iw = fmaxf(brx - tlx, 0.f), ih = fmaxf(bry - tly, 0.f);
                float inter = iw * ih;
                float a2 = (tx1 - tx0) * (ty1 - ty0);
                float iou = inter / (a1 + a2 - inter + 1e-12f);
                if (iou > 0.45f) { ss[i] = NEG_INF; aliveN = false; }
            }
            unsigned int bal = __ballot_sync(0xffffffffu, aliveN);
            if ((tid & 31) == 0) salive[k2 * 32 + (tid >> 5)] = bal;
        }
        __syncthreads();
    }
}

// ---------------- launcher ----------------
extern "C" void kernel_launch(void* const* d_in, const int* in_sizes, int n_in,
                              void* d_out, int out_size) {
    const float* m0 = (const float*)d_in[0];
    const float* m1 = (const float*)d_in[1];
    const float* m2 = (const float*)d_in[2];
    float* out = (float*)d_out;

    cudaFuncSetAttribute(finish_kernel, cudaFuncAttributeMaxDynamicSharedMemorySize, 180224);

    zero_kernel<<<(BATCH * 3 * NLOCP + 255) / 256, 256>>>();
    amax_kernel<<<dim3((VECTOT + 255) / 256, 3, BATCH), 256>>>(m0, m1, m2);
    thr_kernel<<<BATCH, 1024>>>();
    cand_kernel<<<dim3(2, 240, BATCH), 512>>>(m0, m1, m2);
    finish_kernel<<<BATCH, 1024, 180224>>>(m0, m1, m2, out, out_size);
}